// round 16
// baseline (speedup 1.0000x reference)
#include <cuda_runtime.h>
#include <cuda_fp16.h>
#include <math.h>
#include <stdint.h>

// ---------------- Problem constants ----------------
#define Bz   1024
#define Nt   31
#define Dm   576
#define Hh   16
#define Ll   12
#define DH   36
#define FF   2304
#define NC   1000
#define EPSV 1e-5f
#define NEGV -987654321.0f
#define RROWS (Bz * Nt) // 31744

// ---------------- Scratch ----------------
__device__ float  g_h  [(size_t)RROWS * Dm];
__device__ __half g_y  [(size_t)RROWS * Dm];
__device__ __half g_qkv[(size_t)RROWS * 3 * Dm];
__device__ __half g_o  [(size_t)RROWS * Dm];
__device__ __half g_m  [(size_t)RROWS * FF];
__device__ __half g_cls[(size_t)Bz * Dm];

// fp16 weight arena
#define OQKV  0
#define OOUT  11943936
#define OFC1  15925248
#define OFC2  31850496
#define OHEAD 47775744
#define WTOT  48351744
__device__ __half g_w16[WTOT];

// ---------------- helpers ----------------
__device__ __forceinline__ uint32_t cvta_smem(const void* p) {
    uint32_t a;
    asm("{ .reg .u64 t; cvta.to.shared.u64 t, %1; cvt.u32.u64 %0, t; }" : "=r"(a) : "l"(p));
    return a;
}
__device__ __forceinline__ void cpasync16(uint32_t dst, const void* src, uint32_t srcsize) {
    asm volatile("cp.async.cg.shared.global [%0], [%1], 16, %2;"
                 :: "r"(dst), "l"(src), "r"(srcsize));
}
__device__ __forceinline__ void ldm4(uint32_t* a, uint32_t addr) {
    asm volatile("ldmatrix.sync.aligned.m8n8.x4.shared.b16 {%0,%1,%2,%3}, [%4];"
                 : "=r"(a[0]), "=r"(a[1]), "=r"(a[2]), "=r"(a[3]) : "r"(addr));
}
__device__ __forceinline__ void mma16816(float* c, const uint32_t* a, const uint32_t* b) {
    asm volatile(
        "mma.sync.aligned.m16n8k16.row.col.f32.f16.f16.f32 "
        "{%0,%1,%2,%3}, {%4,%5,%6,%7}, {%8,%9}, {%0,%1,%2,%3};"
        : "+f"(c[0]), "+f"(c[1]), "+f"(c[2]), "+f"(c[3])
        : "r"(a[0]), "r"(a[1]), "r"(a[2]), "r"(a[3]), "r"(b[0]), "r"(b[1]));
}
__device__ __forceinline__ float gelu_exact(float x) {
    return 0.5f * x * (1.0f + erff(x * 0.70710678118654752f));
}

// ---------------- fused convert fp32 -> fp16 (single launch) ----------------
__global__ void convert_all(const float* __restrict__ qkv_w,
                            const float* __restrict__ out_w,
                            const float* __restrict__ fc1_w,
                            const float* __restrict__ fc2_w,
                            const float* __restrict__ head_w,
                            __half* __restrict__ w) {
    int stride = gridDim.x * blockDim.x;
    for (size_t i = blockIdx.x * blockDim.x + threadIdx.x; i < WTOT; i += stride) {
        float v;
        if (i < OOUT)       v = qkv_w[i - OQKV];
        else if (i < OFC1)  v = out_w[i - OOUT];
        else if (i < OFC2)  v = fc1_w[i - OFC1];
        else if (i < OHEAD) v = fc2_w[i - OFC2];
        else                v = head_w[i - OHEAD];
        w[i] = __float2half_rn(v);
    }
}

// ---------------- LayerNorm (fp32 in, fp16 out) ----------------
__global__ void ln_kernel(const float* __restrict__ x,
                          const float* __restrict__ w,
                          const float* __restrict__ b,
                          __half* __restrict__ y,
                          int rows, long long in_row_stride) {
    int row = blockIdx.x * (blockDim.x >> 5) + (threadIdx.x >> 5);
    if (row >= rows) return;
    int lane = threadIdx.x & 31;
    const float* xr = x + (long long)row * in_row_stride;
    float v[18];
    float s = 0.f;
#pragma unroll
    for (int i = 0; i < 18; i++) { v[i] = xr[lane + i * 32]; s += v[i]; }
#pragma unroll
    for (int o = 16; o; o >>= 1) s += __shfl_xor_sync(0xffffffffu, s, o);
    float mean = s * (1.0f / Dm);
    float s2 = 0.f;
#pragma unroll
    for (int i = 0; i < 18; i++) { float d = v[i] - mean; s2 += d * d; }
#pragma unroll
    for (int o = 16; o; o >>= 1) s2 += __shfl_xor_sync(0xffffffffu, s2, o);
    float inv = rsqrtf(s2 * (1.0f / Dm) + EPSV);
    __half* yr = y + (long long)row * Dm;
#pragma unroll
    for (int i = 0; i < 18; i++) {
        int d = lane + i * 32;
        yr[d] = __float2half_rn((v[i] - mean) * inv * w[d] + b[d]);
    }
}

// ---------------- Attention: half2 smem, HFMA2 QK, occ-5 (R15 best) ----------
#define QP2 19
#define SP  33

__global__ __launch_bounds__(128, 5)
void attn_kernel(const __half* __restrict__ qkv,
                 const float* __restrict__ scale,
                 __half* __restrict__ o) {
    int b = blockIdx.x;
    int h = blockIdx.y;
    __shared__ __half2 qs[32][QP2];
    __shared__ __half2 ks[32][QP2];
    __shared__ __half2 vs[32][QP2];
    __shared__ float   ss[32][SP];
    int tid = threadIdx.x; // 128

    const __half2* base2 = (const __half2*)(qkv + (long long)b * Nt * (3 * Dm) + h * DH);
    __half2 z2 = __floats2half2_rn(0.f, 0.f);
    for (int idx = tid; idx < 32 * (DH / 2); idx += 128) {
        int n = idx / (DH / 2), dp = idx % (DH / 2);
        __half2 qv = z2, kv = z2, vv = z2;
        if (n < Nt) {
            const __half2* p = base2 + (long long)n * (3 * Dm / 2) + dp;
            qv = p[0];
            kv = p[Dm / 2];
            vv = p[Dm];
        }
        qs[n][dp] = qv;
        ks[n][dp] = kv;
        vs[n][dp] = vv;
    }
    __syncthreads();

    float sc = scale[h];

    // ---- QK: 16(i) x 8(j); per-thread 2 rows x 4 cols; HFMA2 accumulation ----
    {
        int ti = tid >> 3, tj = tid & 7;
        int i0 = ti, i1 = ti + 16, j0 = tj * 4;
        __half2 acc2[2][4];
#pragma unroll
        for (int r = 0; r < 2; r++)
#pragma unroll
            for (int jj = 0; jj < 4; jj++) acc2[r][jj] = z2;
#pragma unroll
        for (int dp = 0; dp < DH / 2; dp++) {
            __half2 q0 = qs[i0][dp];
            __half2 q1 = qs[i1][dp];
#pragma unroll
            for (int jj = 0; jj < 4; jj++) {
                __half2 kv = ks[j0 + jj][dp];
                acc2[0][jj] = __hfma2(q0, kv, acc2[0][jj]);
                acc2[1][jj] = __hfma2(q1, kv, acc2[1][jj]);
            }
        }
#pragma unroll
        for (int r = 0; r < 2; r++) {
            int i = (r == 0) ? i0 : i1;
#pragma unroll
            for (int jj = 0; jj < 4; jj++) {
                int j = j0 + jj;
                float v = __low2float(acc2[r][jj]) + __high2float(acc2[r][jj]);
                ss[i][j] = (i == j) ? NEGV : v * sc;
            }
        }
    }
    __syncthreads();

    // ---- softmax: all 128 threads (32 rows x 4 lanes) ----
    {
        int i = tid >> 2, q = tid & 3;
        int jb = q * 8;
        float mx = -3.4e38f;
#pragma unroll
        for (int jj = 0; jj < 8; jj++) {
            int j = jb + jj;
            if (j < Nt) mx = fmaxf(mx, ss[i][j]);
        }
        mx = fmaxf(mx, __shfl_xor_sync(0xffffffffu, mx, 1));
        mx = fmaxf(mx, __shfl_xor_sync(0xffffffffu, mx, 2));
        float e[8];
        float sum = 0.f;
#pragma unroll
        for (int jj = 0; jj < 8; jj++) {
            int j = jb + jj;
            if (j < Nt) { e[jj] = expf(ss[i][j] - mx); sum += e[jj]; }
            else e[jj] = 0.f;
        }
        sum += __shfl_xor_sync(0xffffffffu, sum, 1);
        sum += __shfl_xor_sync(0xffffffffu, sum, 2);
        float inv = 1.0f / sum;
        __syncthreads();
#pragma unroll
        for (int jj = 0; jj < 8; jj++) {
            int j = jb + jj;
            ss[i][j] = e[jj] * inv;
        }
    }
    __syncthreads();

    // ---- AV: 8(i) x 16(dp) grid; fp32 accumulation ----
    {
        int ti = tid >> 4, tdp = tid & 15;
#pragma unroll
        for (int c = 0; c < 2; c++) {
            int dp = tdp + 16 * c;
            if (dp < DH / 2) {
                float a[4][2];
#pragma unroll
                for (int r = 0; r < 4; r++) { a[r][0] = 0.f; a[r][1] = 0.f; }
#pragma unroll
                for (int j = 0; j < 32; j++) {
                    float2 v = __half22float2(vs[j][dp]);
#pragma unroll
                    for (int r = 0; r < 4; r++) {
                        float w = ss[ti + 8 * r][j];
                        a[r][0] = fmaf(w, v.x, a[r][0]);
                        a[r][1] = fmaf(w, v.y, a[r][1]);
                    }
                }
#pragma unroll
                for (int r = 0; r < 4; r++) {
                    int i = ti + 8 * r;
                    if (i < Nt) {
                        *(__half2*)(o + (long long)(b * Nt + i) * Dm + h * DH + 2 * dp) =
                            __floats2half2_rn(a[r][0], a[r][1]);
                    }
                }
            }
        }
    }
}

// ---------------- HMMA GEMM: BIG TILES for L2 traffic ----------------
// BM=256, BN=144, BK=64, STG=2, 384 threads = 12 warps (4m x 3n),
// warp tile 64x48 (proven shape). smem 115.2KB dynamic -> 1 CTA/SM, 12 warps/SM.
// Per-layer L2 tile traffic: 4.6GB -> 2.74GB.
#define BM 256
#define BN 144
#define BK 64
#define APAD 72
#define GT 384
#define A_ST (BM * APAD * 2)           // 36864 B per stage
#define B_ST (BN * APAD * 2)           // 20736 B per stage
#define SMEMB (2 * (A_ST + B_ST))      // 115200 B

template <bool NG>
__device__ __forceinline__ void load_tile(const __half* A, const __half* W,
                                          int Nout, int K, int m0, int n0, int k0,
                                          uint32_t sa, uint32_t sb, int tid) {
    // A: 256 rows x 8 chunks(16B) = 2048 chunks; 384 threads -> 6 iters (guarded)
#pragma unroll
    for (int i = 0; i < 6; i++) {
        int idx = tid + i * GT;
        if (idx < 2048) {
            int r = idx >> 3, ch = idx & 7;
            const __half* g = A + (size_t)(m0 + r) * K + k0 + ch * 8;
            cpasync16(sa + r * (APAD * 2) + ch * 16, g, 16);
        }
    }
    // B: 144 rows x 8 chunks = 1152 chunks -> 3 exact iters
#pragma unroll
    for (int i = 0; i < 3; i++) {
        int idx = tid + i * GT;
        int r = idx >> 3, ch = idx & 7;
        int rr = n0 + r;
        uint32_t sz = 16;
        if (NG && rr >= Nout) { rr = 0; sz = 0; }
        const __half* g = W + (size_t)rr * K + k0 + ch * 8;
        cpasync16(sb + r * (APAD * 2) + ch * 16, g, sz);
    }
    asm volatile("cp.async.commit_group;" ::: "memory");
}

template <bool BIAS, bool RES, bool GELU, bool HALFOUT, bool NG>
__global__ __launch_bounds__(GT, 1) void hgemm(
    const __half* __restrict__ A, const __half* __restrict__ W,
    const float* __restrict__ bias, const float* __restrict__ resid,
    void* __restrict__ Cout, int M, int Nout, int K) {
    extern __shared__ uint8_t smem[];
    uint32_t sbase = cvta_smem(smem);
    uint32_t sA[2] = { sbase, sbase + A_ST };
    uint32_t sB[2] = { sbase + 2 * A_ST, sbase + 2 * A_ST + B_ST };

    int tid = threadIdx.x, wid = tid >> 5, lane = tid & 31;
    int wm = wid / 3, wn = wid % 3;   // 4m x 3n
    int m0 = blockIdx.y * BM, n0 = blockIdx.x * BN;

    float c[4][6][4];
#pragma unroll
    for (int mi = 0; mi < 4; mi++)
#pragma unroll
        for (int ni = 0; ni < 6; ni++)
#pragma unroll
            for (int j = 0; j < 4; j++) c[mi][ni][j] = 0.f;

    const int T = K / BK;
    load_tile<NG>(A, W, Nout, K, m0, n0, 0, sA[0], sB[0], tid);

    uint32_t aRow = (uint32_t)(wm * 64 + (lane & 15));
    uint32_t aCol8 = (uint32_t)((lane >> 4) * 8);
    int t4 = lane >> 3, r8 = lane & 7;
    uint32_t bBase = (uint32_t)((wn * 48 + (t4 >> 1) * 8 + r8) * APAD + (t4 & 1) * 8);

    for (int t = 0; t < T; t++) {
        asm volatile("cp.async.wait_group 0;" ::: "memory");
        __syncthreads();   // tile t visible; compute of t-1 done before reuse
        if (t + 1 < T) {
            load_tile<NG>(A, W, Nout, K, m0, n0, (t + 1) * BK,
                          sA[(t + 1) & 1], sB[(t + 1) & 1], tid);
        }
        int s = t & 1;
#pragma unroll
        for (int ks = 0; ks < 4; ks++) {
            uint32_t a[4][4], b[6][2];
#pragma unroll
            for (int mi = 0; mi < 4; mi++)
                ldm4(a[mi], sA[s] + ((aRow + mi * 16) * APAD + ks * 16 + aCol8) * 2);
#pragma unroll
            for (int nb = 0; nb < 3; nb++) {
                uint32_t bb[4];
                ldm4(bb, sB[s] + (bBase + nb * 16 * APAD + ks * 16) * 2);
                b[nb * 2 + 0][0] = bb[0]; b[nb * 2 + 0][1] = bb[1];
                b[nb * 2 + 1][0] = bb[2]; b[nb * 2 + 1][1] = bb[3];
            }
#pragma unroll
            for (int mi = 0; mi < 4; mi++)
#pragma unroll
                for (int ni = 0; ni < 6; ni++)
                    mma16816(c[mi][ni], a[mi], b[ni]);
        }
    }

    int rbase = m0 + wm * 64 + (lane >> 2);
    int cbase = n0 + wn * 48 + (lane & 3) * 2;
#pragma unroll
    for (int mi = 0; mi < 4; mi++) {
#pragma unroll
        for (int half = 0; half < 2; half++) {
            size_t row = (size_t)(rbase + mi * 16 + half * 8);
#pragma unroll
            for (int ni = 0; ni < 6; ni++) {
                int col = cbase + ni * 8;
                if (!NG || col + 1 < Nout) {
                    float v0 = c[mi][ni][half * 2 + 0];
                    float v1 = c[mi][ni][half * 2 + 1];
                    if (BIAS) { v0 += bias[col]; v1 += bias[col + 1]; }
                    if (GELU) { v0 = gelu_exact(v0); v1 = gelu_exact(v1); }
                    if (RES) {
                        v0 += resid[row * Nout + col];
                        v1 += resid[row * Nout + col + 1];
                    }
                    if (HALFOUT) {
                        *(__half2*)((__half*)Cout + row * Nout + col) =
                            __floats2half2_rn(v0, v1);
                    } else {
                        *(float2*)((float*)Cout + row * Nout + col) =
                            make_float2(v0, v1);
                    }
                }
            }
        }
    }
}

// ---------------- Host launcher ----------------
extern "C" void kernel_launch(void* const* d_in, const int* in_sizes, int n_in,
                              void* d_out, int out_size) {
    const float* x      = (const float*)d_in[0];
    const float* qkv_w  = (const float*)d_in[1];
    const float* scale  = (const float*)d_in[2];
    const float* out_w  = (const float*)d_in[3];
    const float* out_b  = (const float*)d_in[4];
    const float* ln1_w  = (const float*)d_in[5];
    const float* ln1_b  = (const float*)d_in[6];
    const float* ln2_w  = (const float*)d_in[7];
    const float* ln2_b  = (const float*)d_in[8];
    const float* fc1_w  = (const float*)d_in[9];
    const float* fc1_b  = (const float*)d_in[10];
    const float* fc2_w  = (const float*)d_in[11];
    const float* fc2_b  = (const float*)d_in[12];
    const float* norm_w = (const float*)d_in[13];
    const float* norm_b = (const float*)d_in[14];
    const float* head_w = (const float*)d_in[15];
    const float* head_b = (const float*)d_in[16];
    float* out = (float*)d_out;

    float  *h;
    __half *y, *qkv, *o, *m, *cls, *w16;
    cudaGetSymbolAddress((void**)&h,   g_h);
    cudaGetSymbolAddress((void**)&y,   g_y);
    cudaGetSymbolAddress((void**)&qkv, g_qkv);
    cudaGetSymbolAddress((void**)&o,   g_o);
    cudaGetSymbolAddress((void**)&m,   g_m);
    cudaGetSymbolAddress((void**)&cls, g_cls);
    cudaGetSymbolAddress((void**)&w16, g_w16);

    // allow big dynamic smem (idempotent attribute set; immediate API)
    cudaFuncSetAttribute(hgemm<false, false, false, true,  false>, cudaFuncAttributeMaxDynamicSharedMemorySize, SMEMB);
    cudaFuncSetAttribute(hgemm<true,  true,  false, false, false>, cudaFuncAttributeMaxDynamicSharedMemorySize, SMEMB);
    cudaFuncSetAttribute(hgemm<true,  false, true,  true,  false>, cudaFuncAttributeMaxDynamicSharedMemorySize, SMEMB);
    cudaFuncSetAttribute(hgemm<true,  false, false, false, true >, cudaFuncAttributeMaxDynamicSharedMemorySize, SMEMB);

    cudaMemcpyAsync(h, x, sizeof(float) * (size_t)RROWS * Dm, cudaMemcpyDeviceToDevice);

    convert_all<<<4096, 256>>>(qkv_w, out_w, fc1_w, fc2_w, head_w, w16);

    dim3 gQKV(3 * Dm / BN, RROWS / BM);   // (12, 124)
    dim3 gPROJ(Dm / BN, RROWS / BM);      // (4, 124)
    dim3 gFC1(FF / BN, RROWS / BM);       // (16, 124)
    dim3 gATT(Bz, Hh);
    int lnBlocks = RROWS / 8;

    for (int l = 0; l < Ll; l++) {
        const __half* qw = w16 + OQKV + (size_t)l * 3 * Dm * Dm;
        const __half* ow = w16 + OOUT + (size_t)l * Dm * Dm;
        const __half* w1 = w16 + OFC1 + (size_t)l * FF * Dm;
        const __half* w2 = w16 + OFC2 + (size_t)l * Dm * FF;

        ln_kernel<<<lnBlocks, 256>>>(h, ln1_w + l * Dm, ln1_b + l * Dm, y, RROWS, Dm);
        hgemm<false, false, false, true, false><<<gQKV, GT, SMEMB>>>(
            y, qw, nullptr, nullptr, qkv, RROWS, 3 * Dm, Dm);
        attn_kernel<<<gATT, 128>>>(qkv, scale + l * Hh, o);
        hgemm<true, true, false, false, false><<<gPROJ, GT, SMEMB>>>(
            o, ow, out_b + l * Dm, h, h, RROWS, Dm, Dm);
        ln_kernel<<<lnBlocks, 256>>>(h, ln2_w + l * Dm, ln2_b + l * Dm, y, RROWS, Dm);
        hgemm<true, false, true, true, false><<<gFC1, GT, SMEMB>>>(
            y, w1, fc1_b + l * FF, nullptr, m, RROWS, FF, Dm);
        hgemm<true, true, false, false, false><<<gPROJ, GT, SMEMB>>>(
            m, w2, fc2_b + l * Dm, h, h, RROWS, Dm, FF);
    }

    ln_kernel<<<Bz / 8, 256>>>(h, norm_w, norm_b, cls, Bz, (long long)Nt * Dm);
    dim3 gHEAD((NC + BN - 1) / BN, Bz / BM); // (7, 4)
    hgemm<true, false, false, false, true><<<gHEAD, GT, SMEMB>>>(
        cls, w16 + OHEAD, head_b, nullptr, out, Bz, NC, Dm);
}

// round 17
// speedup vs baseline: 1.2426x; 1.2426x over previous
#include <cuda_runtime.h>
#include <cuda_fp16.h>
#include <math.h>
#include <stdint.h>

// ---------------- Problem constants ----------------
#define Bz   1024
#define Nt   31
#define Dm   576
#define Hh   16
#define Ll   12
#define DH   36
#define FF   2304
#define NC   1000
#define EPSV 1e-5f
#define NEGV -987654321.0f
#define RROWS (Bz * Nt) // 31744

// ---------------- Scratch ----------------
__device__ float  g_h  [(size_t)RROWS * Dm];
__device__ __half g_y  [(size_t)RROWS * Dm];
__device__ __half g_qkv[(size_t)RROWS * 3 * Dm];
__device__ __half g_o  [(size_t)RROWS * Dm];
__device__ __half g_m  [(size_t)RROWS * FF];
__device__ __half g_cls[(size_t)Bz * Dm];

// fp16 weight arena
#define OQKV  0
#define OOUT  11943936
#define OFC1  15925248
#define OFC2  31850496
#define OHEAD 47775744
#define WTOT  48351744
__device__ __half g_w16[WTOT];

// ---------------- helpers ----------------
__device__ __forceinline__ uint32_t cvta_smem(const void* p) {
    uint32_t a;
    asm("{ .reg .u64 t; cvta.to.shared.u64 t, %1; cvt.u32.u64 %0, t; }" : "=r"(a) : "l"(p));
    return a;
}
__device__ __forceinline__ void cpasync16(uint32_t dst, const void* src, uint32_t srcsize) {
    asm volatile("cp.async.cg.shared.global [%0], [%1], 16, %2;"
                 :: "r"(dst), "l"(src), "r"(srcsize));
}
__device__ __forceinline__ void ldm4(uint32_t* a, uint32_t addr) {
    asm volatile("ldmatrix.sync.aligned.m8n8.x4.shared.b16 {%0,%1,%2,%3}, [%4];"
                 : "=r"(a[0]), "=r"(a[1]), "=r"(a[2]), "=r"(a[3]) : "r"(addr));
}
__device__ __forceinline__ void mma16816(float* c, const uint32_t* a, const uint32_t* b) {
    asm volatile(
        "mma.sync.aligned.m16n8k16.row.col.f32.f16.f16.f32 "
        "{%0,%1,%2,%3}, {%4,%5,%6,%7}, {%8,%9}, {%0,%1,%2,%3};"
        : "+f"(c[0]), "+f"(c[1]), "+f"(c[2]), "+f"(c[3])
        : "r"(a[0]), "r"(a[1]), "r"(a[2]), "r"(a[3]), "r"(b[0]), "r"(b[1]));
}
__device__ __forceinline__ float gelu_exact(float x) {
    return 0.5f * x * (1.0f + erff(x * 0.70710678118654752f));
}

// ---------------- fused convert fp32 -> fp16 (single launch) ----------------
__global__ void convert_all(const float* __restrict__ qkv_w,
                            const float* __restrict__ out_w,
                            const float* __restrict__ fc1_w,
                            const float* __restrict__ fc2_w,
                            const float* __restrict__ head_w,
                            __half* __restrict__ w) {
    int stride = gridDim.x * blockDim.x;
    for (size_t i = blockIdx.x * blockDim.x + threadIdx.x; i < WTOT; i += stride) {
        float v;
        if (i < OOUT)       v = qkv_w[i - OQKV];
        else if (i < OFC1)  v = out_w[i - OOUT];
        else if (i < OFC2)  v = fc1_w[i - OFC1];
        else if (i < OHEAD) v = fc2_w[i - OFC2];
        else                v = head_w[i - OHEAD];
        w[i] = __float2half_rn(v);
    }
}

// ---------------- LayerNorm (fp32 in, fp16 out), float4 vectorized ----------
__global__ void ln_kernel(const float* __restrict__ x,
                          const float* __restrict__ w,
                          const float* __restrict__ b,
                          __half* __restrict__ y,
                          int rows, long long in_row_stride) {
    int row = blockIdx.x * (blockDim.x >> 5) + (threadIdx.x >> 5);
    if (row >= rows) return;
    int lane = threadIdx.x & 31;
    const float4* xr4 = (const float4*)(x + (long long)row * in_row_stride);
    float4 v[5];
    float s = 0.f;
#pragma unroll
    for (int i = 0; i < 4; i++) {
        v[i] = xr4[lane + i * 32];
        s += (v[i].x + v[i].y) + (v[i].z + v[i].w);
    }
    bool tail = (lane < 16);
    if (tail) {
        v[4] = xr4[128 + lane];
        s += (v[4].x + v[4].y) + (v[4].z + v[4].w);
    }
#pragma unroll
    for (int o = 16; o; o >>= 1) s += __shfl_xor_sync(0xffffffffu, s, o);
    float mean = s * (1.0f / Dm);
    float s2 = 0.f;
#pragma unroll
    for (int i = 0; i < 4; i++) {
        float dx = v[i].x - mean, dy = v[i].y - mean;
        float dz = v[i].z - mean, dw = v[i].w - mean;
        s2 += (dx * dx + dy * dy) + (dz * dz + dw * dw);
    }
    if (tail) {
        float dx = v[4].x - mean, dy = v[4].y - mean;
        float dz = v[4].z - mean, dw = v[4].w - mean;
        s2 += (dx * dx + dy * dy) + (dz * dz + dw * dw);
    }
#pragma unroll
    for (int o = 16; o; o >>= 1) s2 += __shfl_xor_sync(0xffffffffu, s2, o);
    float inv = rsqrtf(s2 * (1.0f / Dm) + EPSV);
    __half* yr = y + (long long)row * Dm;
#pragma unroll
    for (int i = 0; i < 4; i++) {
        int d = (lane + i * 32) * 4;
        float4 wv = *(const float4*)(w + d);
        float4 bv = *(const float4*)(b + d);
        __half2 h0 = __floats2half2_rn((v[i].x - mean) * inv * wv.x + bv.x,
                                       (v[i].y - mean) * inv * wv.y + bv.y);
        __half2 h1 = __floats2half2_rn((v[i].z - mean) * inv * wv.z + bv.z,
                                       (v[i].w - mean) * inv * wv.w + bv.w);
        *(__half2*)(yr + d)     = h0;
        *(__half2*)(yr + d + 2) = h1;
    }
    if (tail) {
        int d = 512 + lane * 4;
        float4 wv = *(const float4*)(w + d);
        float4 bv = *(const float4*)(b + d);
        __half2 h0 = __floats2half2_rn((v[4].x - mean) * inv * wv.x + bv.x,
                                       (v[4].y - mean) * inv * wv.y + bv.y);
        __half2 h1 = __floats2half2_rn((v[4].z - mean) * inv * wv.z + bv.z,
                                       (v[4].w - mean) * inv * wv.w + bv.w);
        *(__half2*)(yr + d)     = h0;
        *(__half2*)(yr + d + 2) = h1;
    }
}

// ---------------- Attention: half2 smem, HFMA2 QK, balanced AV ----------------
#define QP2 19
#define SP  33

__global__ __launch_bounds__(128, 5)
void attn_kernel(const __half* __restrict__ qkv,
                 const float* __restrict__ scale,
                 __half* __restrict__ o) {
    int b = blockIdx.x;
    int h = blockIdx.y;
    __shared__ __half2 qs[32][QP2];
    __shared__ __half2 ks[32][QP2];
    __shared__ __half2 vs[32][QP2];
    __shared__ float   ss[32][SP];
    int tid = threadIdx.x; // 128

    const __half2* base2 = (const __half2*)(qkv + (long long)b * Nt * (3 * Dm) + h * DH);
    __half2 z2 = __floats2half2_rn(0.f, 0.f);
    for (int idx = tid; idx < 32 * (DH / 2); idx += 128) {
        int n = idx / (DH / 2), dp = idx % (DH / 2);
        __half2 qv = z2, kv = z2, vv = z2;
        if (n < Nt) {
            const __half2* p = base2 + (long long)n * (3 * Dm / 2) + dp;
            qv = p[0];
            kv = p[Dm / 2];
            vv = p[Dm];
        }
        qs[n][dp] = qv;
        ks[n][dp] = kv;
        vs[n][dp] = vv;
    }
    __syncthreads();

    float sc = scale[h];

    // ---- QK: 16(i) x 8(j); per-thread 2 rows x 4 cols; HFMA2 accumulation ----
    {
        int ti = tid >> 3, tj = tid & 7;
        int i0 = ti, i1 = ti + 16, j0 = tj * 4;
        __half2 acc2[2][4];
#pragma unroll
        for (int r = 0; r < 2; r++)
#pragma unroll
            for (int jj = 0; jj < 4; jj++) acc2[r][jj] = z2;
#pragma unroll
        for (int dp = 0; dp < DH / 2; dp++) {
            __half2 q0 = qs[i0][dp];
            __half2 q1 = qs[i1][dp];
#pragma unroll
            for (int jj = 0; jj < 4; jj++) {
                __half2 kv = ks[j0 + jj][dp];
                acc2[0][jj] = __hfma2(q0, kv, acc2[0][jj]);
                acc2[1][jj] = __hfma2(q1, kv, acc2[1][jj]);
            }
        }
#pragma unroll
        for (int r = 0; r < 2; r++) {
            int i = (r == 0) ? i0 : i1;
#pragma unroll
            for (int jj = 0; jj < 4; jj++) {
                int j = j0 + jj;
                float v = __low2float(acc2[r][jj]) + __high2float(acc2[r][jj]);
                ss[i][j] = (i == j) ? NEGV : v * sc;
            }
        }
    }
    __syncthreads();

    // ---- softmax: all 128 threads (32 rows x 4 lanes) ----
    {
        int i = tid >> 2, q = tid & 3;
        int jb = q * 8;
        float mx = -3.4e38f;
#pragma unroll
        for (int jj = 0; jj < 8; jj++) {
            int j = jb + jj;
            if (j < Nt) mx = fmaxf(mx, ss[i][j]);
        }
        mx = fmaxf(mx, __shfl_xor_sync(0xffffffffu, mx, 1));
        mx = fmaxf(mx, __shfl_xor_sync(0xffffffffu, mx, 2));
        float e[8];
        float sum = 0.f;
#pragma unroll
        for (int jj = 0; jj < 8; jj++) {
            int j = jb + jj;
            if (j < Nt) { e[jj] = expf(ss[i][j] - mx); sum += e[jj]; }
            else e[jj] = 0.f;
        }
        sum += __shfl_xor_sync(0xffffffffu, sum, 1);
        sum += __shfl_xor_sync(0xffffffffu, sum, 2);
        float inv = 1.0f / sum;
        __syncthreads();
#pragma unroll
        for (int jj = 0; jj < 8; jj++) {
            int j = jb + jj;
            ss[i][j] = e[jj] * inv;
        }
    }
    __syncthreads();

    // ---- AV: balanced 16(i-groups) x 8(dp) grid ----
    // thread: rows {it, it+16}, half2-cols {2*t8, 2*t8+1} (+ col 16+t8 if t8<2)
    {
        int it = tid >> 3, t8 = tid & 7;
        int dp0 = 2 * t8, dp1 = 2 * t8 + 1, dp2 = 16 + t8;
        bool has2 = (t8 < 2);
        float a[2][3][2];
#pragma unroll
        for (int r = 0; r < 2; r++)
#pragma unroll
            for (int k = 0; k < 3; k++) { a[r][k][0] = 0.f; a[r][k][1] = 0.f; }
#pragma unroll
        for (int j = 0; j < 32; j++) {
            float w0 = ss[it][j];
            float w1 = ss[it + 16][j];
            float2 v0 = __half22float2(vs[j][dp0]);
            float2 v1 = __half22float2(vs[j][dp1]);
            a[0][0][0] = fmaf(w0, v0.x, a[0][0][0]);
            a[0][0][1] = fmaf(w0, v0.y, a[0][0][1]);
            a[0][1][0] = fmaf(w0, v1.x, a[0][1][0]);
            a[0][1][1] = fmaf(w0, v1.y, a[0][1][1]);
            a[1][0][0] = fmaf(w1, v0.x, a[1][0][0]);
            a[1][0][1] = fmaf(w1, v0.y, a[1][0][1]);
            a[1][1][0] = fmaf(w1, v1.x, a[1][1][0]);
            a[1][1][1] = fmaf(w1, v1.y, a[1][1][1]);
            if (has2) {
                float2 v2 = __half22float2(vs[j][dp2]);
                a[0][2][0] = fmaf(w0, v2.x, a[0][2][0]);
                a[0][2][1] = fmaf(w0, v2.y, a[0][2][1]);
                a[1][2][0] = fmaf(w1, v2.x, a[1][2][0]);
                a[1][2][1] = fmaf(w1, v2.y, a[1][2][1]);
            }
        }
#pragma unroll
        for (int r = 0; r < 2; r++) {
            int i = it + 16 * r;
            if (i < Nt) {
                __half* op = o + (long long)(b * Nt + i) * Dm + h * DH;
                *(__half2*)(op + 2 * dp0) = __floats2half2_rn(a[r][0][0], a[r][0][1]);
                *(__half2*)(op + 2 * dp1) = __floats2half2_rn(a[r][1][0], a[r][1][1]);
                if (has2)
                    *(__half2*)(op + 2 * dp2) = __floats2half2_rn(a[r][2][0], a[r][2][1]);
            }
        }
    }
}

// ---------------- HMMA GEMM (R11/R15 config): C = A * W^T ----------------
#define BM 128
#define BN 96
#define BK 64
#define STG 2
#define APAD 72
#define GT 128

template <bool NG>
__device__ __forceinline__ void load_tile(const __half* A, const __half* W,
                                          int Nout, int K, int m0, int n0, int k0,
                                          uint32_t sa, uint32_t sb, int tid) {
#pragma unroll
    for (int i = 0; i < 8; i++) {
        int idx = tid + i * GT;
        int r = idx >> 3, ch = idx & 7;
        const __half* g = A + (size_t)(m0 + r) * K + k0 + ch * 8;
        cpasync16(sa + r * (APAD * 2) + ch * 16, g, 16);
    }
#pragma unroll
    for (int i = 0; i < 6; i++) {
        int idx = tid + i * GT;
        int r = idx >> 3, ch = idx & 7;
        int rr = n0 + r;
        uint32_t sz = 16;
        if (NG && rr >= Nout) { rr = 0; sz = 0; }
        const __half* g = W + (size_t)rr * K + k0 + ch * 8;
        cpasync16(sb + r * (APAD * 2) + ch * 16, g, sz);
    }
    asm volatile("cp.async.commit_group;" ::: "memory");
}

template <bool BIAS, bool RES, bool GELU, bool HALFOUT, bool NG>
__global__ __launch_bounds__(GT, 3) void hgemm(
    const __half* __restrict__ A, const __half* __restrict__ W,
    const float* __restrict__ bias, const float* __restrict__ resid,
    void* __restrict__ Cout, int M, int Nout, int K) {
    __shared__ __half As[STG][BM][APAD];
    __shared__ __half Bs[STG][BN][APAD];
    int tid = threadIdx.x, wid = tid >> 5, lane = tid & 31;
    int wm = wid >> 1, wn = wid & 1;
    int m0 = blockIdx.y * BM, n0 = blockIdx.x * BN;

    uint32_t sA[STG], sB[STG];
#pragma unroll
    for (int s = 0; s < STG; s++) {
        sA[s] = cvta_smem(&As[s][0][0]);
        sB[s] = cvta_smem(&Bs[s][0][0]);
    }

    float c[4][6][4];
#pragma unroll
    for (int mi = 0; mi < 4; mi++)
#pragma unroll
        for (int ni = 0; ni < 6; ni++)
#pragma unroll
            for (int j = 0; j < 4; j++) c[mi][ni][j] = 0.f;

    const int T = K / BK;
    load_tile<NG>(A, W, Nout, K, m0, n0, 0, sA[0], sB[0], tid);

    uint32_t aRow = (uint32_t)(wm * 64 + (lane & 15));
    uint32_t aCol8 = (uint32_t)((lane >> 4) * 8);
    int t4 = lane >> 3, r8 = lane & 7;
    uint32_t bBase = (uint32_t)((wn * 48 + (t4 >> 1) * 8 + r8) * APAD + (t4 & 1) * 8);

    for (int t = 0; t < T; t++) {
        asm volatile("cp.async.wait_group 0;" ::: "memory");
        __syncthreads();
        if (t + 1 < T) {
            load_tile<NG>(A, W, Nout, K, m0, n0, (t + 1) * BK,
                          sA[(t + 1) & 1], sB[(t + 1) & 1], tid);
        }
        int s = t & 1;
#pragma unroll
        for (int ks = 0; ks < 4; ks++) {
            uint32_t a[4][4], b[6][2];
#pragma unroll
            for (int mi = 0; mi < 4; mi++)
                ldm4(a[mi], sA[s] + ((aRow + mi * 16) * APAD + ks * 16 + aCol8) * 2);
#pragma unroll
            for (int nb = 0; nb < 3; nb++) {
                uint32_t bb[4];
                ldm4(bb, sB[s] + (bBase + nb * 16 * APAD + ks * 16) * 2);
                b[nb * 2 + 0][0] = bb[0]; b[nb * 2 + 0][1] = bb[1];
                b[nb * 2 + 1][0] = bb[2]; b[nb * 2 + 1][1] = bb[3];
            }
#pragma unroll
            for (int mi = 0; mi < 4; mi++)
#pragma unroll
                for (int ni = 0; ni < 6; ni++)
                    mma16816(c[mi][ni], a[mi], b[ni]);
        }
    }

    int rbase = m0 + wm * 64 + (lane >> 2);
    int cbase = n0 + wn * 48 + (lane & 3) * 2;
#pragma unroll
    for (int mi = 0; mi < 4; mi++) {
#pragma unroll
        for (int half = 0; half < 2; half++) {
            size_t row = (size_t)(rbase + mi * 16 + half * 8);
#pragma unroll
            for (int ni = 0; ni < 6; ni++) {
                int col = cbase + ni * 8;
                if (!NG || col + 1 < Nout) {
                    float v0 = c[mi][ni][half * 2 + 0];
                    float v1 = c[mi][ni][half * 2 + 1];
                    if (BIAS) { v0 += bias[col]; v1 += bias[col + 1]; }
                    if (GELU) { v0 = gelu_exact(v0); v1 = gelu_exact(v1); }
                    if (RES) {
                        v0 += resid[row * Nout + col];
                        v1 += resid[row * Nout + col + 1];
                    }
                    if (HALFOUT) {
                        *(__half2*)((__half*)Cout + row * Nout + col) =
                            __floats2half2_rn(v0, v1);
                    } else {
                        *(float2*)((float*)Cout + row * Nout + col) =
                            make_float2(v0, v1);
                    }
                }
            }
        }
    }
}

// ---------------- Host launcher ----------------
extern "C" void kernel_launch(void* const* d_in, const int* in_sizes, int n_in,
                              void* d_out, int out_size) {
    const float* x      = (const float*)d_in[0];
    const float* qkv_w  = (const float*)d_in[1];
    const float* scale  = (const float*)d_in[2];
    const float* out_w  = (const float*)d_in[3];
    const float* out_b  = (const float*)d_in[4];
    const float* ln1_w  = (const float*)d_in[5];
    const float* ln1_b  = (const float*)d_in[6];
    const float* ln2_w  = (const float*)d_in[7];
    const float* ln2_b  = (const float*)d_in[8];
    const float* fc1_w  = (const float*)d_in[9];
    const float* fc1_b  = (const float*)d_in[10];
    const float* fc2_w  = (const float*)d_in[11];
    const float* fc2_b  = (const float*)d_in[12];
    const float* norm_w = (const float*)d_in[13];
    const float* norm_b = (const float*)d_in[14];
    const float* head_w = (const float*)d_in[15];
    const float* head_b = (const float*)d_in[16];
    float* out = (float*)d_out;

    float  *h;
    __half *y, *qkv, *o, *m, *cls, *w16;
    cudaGetSymbolAddress((void**)&h,   g_h);
    cudaGetSymbolAddress((void**)&y,   g_y);
    cudaGetSymbolAddress((void**)&qkv, g_qkv);
    cudaGetSymbolAddress((void**)&o,   g_o);
    cudaGetSymbolAddress((void**)&m,   g_m);
    cudaGetSymbolAddress((void**)&cls, g_cls);
    cudaGetSymbolAddress((void**)&w16, g_w16);

    cudaMemcpyAsync(h, x, sizeof(float) * (size_t)RROWS * Dm, cudaMemcpyDeviceToDevice);

    convert_all<<<4096, 256>>>(qkv_w, out_w, fc1_w, fc2_w, head_w, w16);

    dim3 gQKV(3 * Dm / BN, RROWS / BM);   // (18, 248)
    dim3 gPROJ(Dm / BN, RROWS / BM);      // (6, 248)
    dim3 gFC1(FF / BN, RROWS / BM);       // (24, 248)
    dim3 gATT(Bz, Hh);
    int lnBlocks = RROWS / 8;

    for (int l = 0; l < Ll; l++) {
        const __half* qw = w16 + OQKV + (size_t)l * 3 * Dm * Dm;
        const __half* ow = w16 + OOUT + (size_t)l * Dm * Dm;
        const __half* w1 = w16 + OFC1 + (size_t)l * FF * Dm;
        const __half* w2 = w16 + OFC2 + (size_t)l * Dm * FF;

        ln_kernel<<<lnBlocks, 256>>>(h, ln1_w + l * Dm, ln1_b + l * Dm, y, RROWS, Dm);
        hgemm<false, false, false, true, false><<<gQKV, GT>>>(
            y, qw, nullptr, nullptr, qkv, RROWS, 3 * Dm, Dm);
        attn_kernel<<<gATT, 128>>>(qkv, scale + l * Hh, o);
        hgemm<true, true, false, false, false><<<gPROJ, GT>>>(
            o, ow, out_b + l * Dm, h, h, RROWS, Dm, Dm);
        ln_kernel<<<lnBlocks, 256>>>(h, ln2_w + l * Dm, ln2_b + l * Dm, y, RROWS, Dm);
        hgemm<true, false, true, true, false><<<gFC1, GT>>>(
            y, w1, fc1_b + l * FF, nullptr, m, RROWS, FF, Dm);
        hgemm<true, true, false, false, false><<<gPROJ, GT>>>(
            m, w2, fc2_b + l * Dm, h, h, RROWS, Dm, FF);
    }

    ln_kernel<<<Bz / 8, 256>>>(h, norm_w, norm_b, cls, Bz, (long long)Nt * Dm);
    dim3 gHEAD((NC + BN - 1) / BN, Bz / BM); // (11, 8)
    hgemm<true, false, false, false, true><<<gHEAD, GT>>>(
        cls, w16 + OHEAD, head_b, nullptr, out, Bz, NC, Dm);
}